// round 2
// baseline (speedup 1.0000x reference)
#include <cuda_runtime.h>
#include <math.h>

#define BATCH 65536
#define NC 100
#define RT 16          // rows per block in k1
#define XP 1001        // padded x pitch in shared (gcd(1001,32)=1)

// scratch: err transposed [cluster][row] so k2 reads coalesced
__device__ float g_errT[(size_t)NC * BATCH];

// ---------------------------------------------------------------------------
// Kernel 1: per-cluster autoencoders -> err[c][row]
// 256 threads, 16 rows staged in shared, each thread handles (cluster, 4 rows)
// ---------------------------------------------------------------------------
__global__ __launch_bounds__(256, 2) void k1_cluster(
    const float* __restrict__ x, const int* __restrict__ feat_idx,
    const float* __restrict__ W_enc, const float* __restrict__ b_enc,
    const float* __restrict__ W_dec, const float* __restrict__ b_dec)
{
    extern __shared__ float smem[];
    float* sx  = smem;                 // RT*XP = 16016 floats
    float* sWe = sx + RT * XP;         // 5000: [(m*5+j)*100 + c]
    float* sbe = sWe + 5000;           // 500:  [j*100 + c]
    float* sWd = sbe + 500;            // 5000: [(j*10+m)*100 + c]
    float* sbd = sWd + 5000;           // 1000: [m*100 + c]
    int*   sfid = (int*)(sbd + 1000);  // 1000

    const int tid  = threadIdx.x;
    const int row0 = blockIdx.x * RT;

    // stage weights transposed so lanes (consecutive c) hit stride-1 banks
    for (int i = tid; i < 5000; i += 256) {
        int c = i / 50, r = i % 50, m = r / 5, j = r % 5;
        sWe[(m * 5 + j) * 100 + c] = W_enc[i];
    }
    for (int i = tid; i < 500; i += 256) {
        int c = i / 5, j = i % 5;
        sbe[j * 100 + c] = b_enc[i];
    }
    for (int i = tid; i < 5000; i += 256) {
        int c = i / 50, r = i % 50, j = r / 10, m = r % 10;
        sWd[(j * 10 + m) * 100 + c] = W_dec[i];
    }
    for (int i = tid; i < 1000; i += 256) {
        int c = i / 10, m = i % 10;
        sbd[m * 100 + c] = b_dec[i];
    }
    for (int i = tid; i < 1000; i += 256) sfid[i] = feat_idx[i];

    // stage 16 x-rows, vectorized loads (row = 250 float4)
    const float4* xv = (const float4*)(x + (size_t)row0 * 1000);
    for (int i = tid; i < RT * 250; i += 256) {
        int r = i / 250, c4 = i % 250;
        float4 v = xv[r * 250 + c4];
        float* d = sx + r * XP + c4 * 4;
        d[0] = v.x; d[1] = v.y; d[2] = v.z; d[3] = v.w;
    }
    __syncthreads();

    // 400 tasks: (cluster c, row-quad q)
    for (int task = tid; task < 400; task += 256) {
        const int c = task % 100;
        const int q = task / 100;
        const float* xq = sx + q * 4 * XP;

        int fid[10];
        #pragma unroll
        for (int m = 0; m < 10; m++) fid[m] = sfid[c * 10 + m];

        float xg[4][10];
        #pragma unroll
        for (int m = 0; m < 10; m++)
            #pragma unroll
            for (int r = 0; r < 4; r++)
                xg[r][m] = xq[r * XP + fid[m]];

        float h[4][5];
        #pragma unroll
        for (int j = 0; j < 5; j++) {
            float b = sbe[j * 100 + c];
            #pragma unroll
            for (int r = 0; r < 4; r++) h[r][j] = b;
        }
        #pragma unroll
        for (int m = 0; m < 10; m++)
            #pragma unroll
            for (int j = 0; j < 5; j++) {
                float w = sWe[(m * 5 + j) * 100 + c];
                #pragma unroll
                for (int r = 0; r < 4; r++) h[r][j] = fmaf(xg[r][m], w, h[r][j]);
            }
        #pragma unroll
        for (int j = 0; j < 5; j++)
            #pragma unroll
            for (int r = 0; r < 4; r++) h[r][j] = fmaxf(h[r][j], 0.f);

        float acc[4] = {0.f, 0.f, 0.f, 0.f};
        #pragma unroll
        for (int m = 0; m < 10; m++) {
            float b = sbd[m * 100 + c];
            float rec[4];
            #pragma unroll
            for (int r = 0; r < 4; r++) rec[r] = b;
            #pragma unroll
            for (int j = 0; j < 5; j++) {
                float w = sWd[(j * 10 + m) * 100 + c];
                #pragma unroll
                for (int r = 0; r < 4; r++) rec[r] = fmaf(h[r][j], w, rec[r]);
            }
            #pragma unroll
            for (int r = 0; r < 4; r++) {
                float d = xg[r][m] - rec[r];
                acc[r] = fmaf(d, d, acc[r]);
            }
        }
        float4 o;
        o.x = sqrtf(acc[0] * 0.1f);
        o.y = sqrtf(acc[1] * 0.1f);
        o.z = sqrtf(acc[2] * 0.1f);
        o.w = sqrtf(acc[3] * 0.1f);
        *(float4*)&g_errT[(size_t)c * BATCH + row0 + q * 4] = o;
    }
}

// ---------------------------------------------------------------------------
// Kernel 2: meta autoencoder over err[row][0..99] -> sigmoid(final_error)
// thread handles 2 rows; err reads are fully coalesced (transposed scratch)
// ---------------------------------------------------------------------------
__global__ __launch_bounds__(128) void k2_meta(
    const float* __restrict__ We1, const float* __restrict__ be1,
    const float* __restrict__ Wd1, const float* __restrict__ bd1,
    float* __restrict__ out)
{
    __shared__ float sWe1[NC * 50];   // [c*50+j]
    __shared__ float sbe1[50];
    __shared__ float sWd1[50 * NC];   // [j*100+c]
    __shared__ float sbd1[NC];

    const int tid = threadIdx.x;
    for (int i = tid; i < NC * 50; i += 128) sWe1[i] = We1[i];
    for (int i = tid; i < NC * 50; i += 128) sWd1[i] = Wd1[i];
    if (tid < 50)  sbe1[tid] = be1[tid];
    if (tid < NC)  sbd1[tid] = bd1[tid];
    __syncthreads();

    const int r0 = blockIdx.x * 256 + tid;
    const int r1 = r0 + 128;

    float hm0[50], hm1[50];
    #pragma unroll
    for (int j = 0; j < 50; j++) { float b = sbe1[j]; hm0[j] = b; hm1[j] = b; }

    for (int c = 0; c < 100; c++) {
        float e0 = g_errT[(size_t)c * BATCH + r0];
        float e1 = g_errT[(size_t)c * BATCH + r1];
        const float* w = sWe1 + c * 50;
        #pragma unroll
        for (int j = 0; j < 50; j++) {
            float wv = w[j];
            hm0[j] = fmaf(e0, wv, hm0[j]);
            hm1[j] = fmaf(e1, wv, hm1[j]);
        }
    }
    #pragma unroll
    for (int j = 0; j < 50; j++) {
        hm0[j] = fmaxf(hm0[j], 0.f);
        hm1[j] = fmaxf(hm1[j], 0.f);
    }

    float acc0 = 0.f, acc1 = 0.f;
    for (int c = 0; c < 100; c++) {
        float b = sbd1[c];
        float rec0 = b, rec1 = b;
        #pragma unroll
        for (int j = 0; j < 50; j++) {
            float wv = sWd1[j * 100 + c];
            rec0 = fmaf(hm0[j], wv, rec0);
            rec1 = fmaf(hm1[j], wv, rec1);
        }
        float e0 = g_errT[(size_t)c * BATCH + r0];
        float e1 = g_errT[(size_t)c * BATCH + r1];
        float d0 = e0 - rec0, d1 = e1 - rec1;
        acc0 = fmaf(d0, d0, acc0);
        acc1 = fmaf(d1, d1, acc1);
    }
    float f0 = sqrtf(acc0 * 0.01f);
    float f1 = sqrtf(acc1 * 0.01f);
    out[r0] = 1.f / (1.f + __expf(-f0));
    out[r1] = 1.f / (1.f + __expf(-f1));
}

extern "C" void kernel_launch(void* const* d_in, const int* in_sizes, int n_in,
                              void* d_out, int out_size)
{
    const float* x        = (const float*)d_in[0];
    const int*   feat_idx = (const int*)  d_in[1];
    const float* W_enc    = (const float*)d_in[2];
    const float* b_enc    = (const float*)d_in[3];
    const float* W_dec    = (const float*)d_in[4];
    const float* b_dec    = (const float*)d_in[5];
    const float* We1      = (const float*)d_in[6];
    const float* be1      = (const float*)d_in[7];
    const float* Wd1      = (const float*)d_in[8];
    const float* bd1      = (const float*)d_in[9];
    float* out = (float*)d_out;

    const int smem1 = (RT * XP + 5000 + 500 + 5000 + 1000) * 4 + 1000 * 4; // 114064 B
    cudaFuncSetAttribute(k1_cluster, cudaFuncAttributeMaxDynamicSharedMemorySize, smem1);

    k1_cluster<<<BATCH / RT, 256, smem1>>>(x, feat_idx, W_enc, b_enc, W_dec, b_dec);
    k2_meta<<<BATCH / 256, 128>>>(We1, be1, Wd1, bd1, out);
}

// round 3
// speedup vs baseline: 1.3991x; 1.3991x over previous
#include <cuda_runtime.h>
#include <math.h>

#define BATCH 65536
#define NC 100
#define RT 16           // rows per tile in k1
#define XP 1001         // padded x pitch in shared (1001 mod 32 = 9, odd -> conflict-free row strides)
#define K1_THREADS 224
#define K1_BLOCKS 296   // 2 CTAs/SM * 148 SMs, persistent

// scratch: err transposed [cluster][row] so k2 reads coalesced
__device__ float g_errT[(size_t)NC * BATCH];

// ---------------- f32x2 helpers ----------------
__device__ __forceinline__ unsigned long long pk2(float lo, float hi) {
    unsigned long long r;
    asm("mov.b64 %0, {%1, %2};" : "=l"(r) : "f"(lo), "f"(hi));
    return r;
}
__device__ __forceinline__ void upk2(float& lo, float& hi, unsigned long long v) {
    asm("mov.b64 {%0, %1}, %2;" : "=f"(lo), "=f"(hi) : "l"(v));
}
__device__ __forceinline__ unsigned long long ffma2(unsigned long long a,
                                                    unsigned long long b,
                                                    unsigned long long c) {
    unsigned long long d;
    asm("fma.rn.f32x2 %0, %1, %2, %3;" : "=l"(d) : "l"(a), "l"(b), "l"(c));
    return d;
}

// ---------------------------------------------------------------------------
// Kernel 1: per-cluster autoencoders -> errT[c][row]. Persistent blocks:
// weights staged ONCE (plain copy, natural layout), then loop over row tiles.
// Task mapping: c = task>>2, q = task&3  (8 clusters per warp, 4 row-quads)
// -> weight LDS conflict-free (8 distinct addrs, stride 50), fid shared by 4 lanes.
// ---------------------------------------------------------------------------
__global__ __launch_bounds__(K1_THREADS, 2) void k1_cluster(
    const float* __restrict__ x, const int* __restrict__ feat_idx,
    const float* __restrict__ W_enc, const float* __restrict__ b_enc,
    const float* __restrict__ W_dec, const float* __restrict__ b_dec)
{
    extern __shared__ float smem[];
    float* sx  = smem;                 // RT*XP = 16016 floats
    float* sWe = sx + RT * XP;         // 5000: natural [c][m][j]
    float* sbe = sWe + 5000;           // 500:  [c][j]
    float* sWd = sbe + 500;            // 5000: [c][j][m]
    float* sbd = sWd + 5000;           // 1000: [c][m]
    int*   sfid = (int*)(sbd + 1000);  // 1000: [c][m]

    const int tid = threadIdx.x;

    // one-time weight staging: straight copies, no index math
    for (int i = tid; i < 5000; i += K1_THREADS) sWe[i] = W_enc[i];
    for (int i = tid; i < 500;  i += K1_THREADS) sbe[i] = b_enc[i];
    for (int i = tid; i < 5000; i += K1_THREADS) sWd[i] = W_dec[i];
    for (int i = tid; i < 1000; i += K1_THREADS) sbd[i] = b_dec[i];
    for (int i = tid; i < 1000; i += K1_THREADS) sfid[i] = feat_idx[i];

    const int n_tiles = BATCH / RT;    // 4096
    for (int t = blockIdx.x; t < n_tiles; t += K1_BLOCKS) {
        const int row0 = t * RT;
        __syncthreads();   // protect sx from previous tile's readers

        // stage 16 x-rows, vectorized (row = 250 float4)
        const float4* xv = (const float4*)(x + (size_t)row0 * 1000);
        for (int i = tid; i < RT * 250; i += K1_THREADS) {
            int r = i / 250, c4 = i % 250;
            float4 v = xv[r * 250 + c4];
            float* d = sx + r * XP + c4 * 4;
            d[0] = v.x; d[1] = v.y; d[2] = v.z; d[3] = v.w;
        }
        __syncthreads();

        // 400 tasks: (cluster c, row-quad q)
        for (int task = tid; task < 4 * NC; task += K1_THREADS) {
            const int c = task >> 2;
            const int q = task & 3;
            const float* xq = sx + q * 4 * XP;

            int fid[10];
            #pragma unroll
            for (int m = 0; m < 10; m++) fid[m] = sfid[c * 10 + m];

            float xg[4][10];
            #pragma unroll
            for (int m = 0; m < 10; m++)
                #pragma unroll
                for (int r = 0; r < 4; r++)
                    xg[r][m] = xq[r * XP + fid[m]];

            float h[4][5];
            #pragma unroll
            for (int j = 0; j < 5; j++) {
                float b = sbe[c * 5 + j];
                #pragma unroll
                for (int r = 0; r < 4; r++) h[r][j] = b;
            }
            #pragma unroll
            for (int m = 0; m < 10; m++)
                #pragma unroll
                for (int j = 0; j < 5; j++) {
                    float w = sWe[c * 50 + m * 5 + j];
                    #pragma unroll
                    for (int r = 0; r < 4; r++) h[r][j] = fmaf(xg[r][m], w, h[r][j]);
                }
            #pragma unroll
            for (int j = 0; j < 5; j++)
                #pragma unroll
                for (int r = 0; r < 4; r++) h[r][j] = fmaxf(h[r][j], 0.f);

            float acc[4] = {0.f, 0.f, 0.f, 0.f};
            #pragma unroll
            for (int m = 0; m < 10; m++) {
                float b = sbd[c * 10 + m];
                float rec[4];
                #pragma unroll
                for (int r = 0; r < 4; r++) rec[r] = b;
                #pragma unroll
                for (int j = 0; j < 5; j++) {
                    float w = sWd[c * 50 + j * 10 + m];
                    #pragma unroll
                    for (int r = 0; r < 4; r++) rec[r] = fmaf(h[r][j], w, rec[r]);
                }
                #pragma unroll
                for (int r = 0; r < 4; r++) {
                    float d = xg[r][m] - rec[r];
                    acc[r] = fmaf(d, d, acc[r]);
                }
            }
            float4 o;
            o.x = sqrtf(acc[0] * 0.1f);
            o.y = sqrtf(acc[1] * 0.1f);
            o.z = sqrtf(acc[2] * 0.1f);
            o.w = sqrtf(acc[3] * 0.1f);
            *(float4*)&g_errT[(size_t)c * BATCH + row0 + q * 4] = o;
        }
    }
}

// ---------------------------------------------------------------------------
// Kernel 2: meta autoencoder. 1 row/thread, fma.rn.f32x2 packed over j-pairs.
// Weights in shared, j-contiguous so LDS.64 feeds FFMA2 directly.
// ---------------------------------------------------------------------------
__global__ __launch_bounds__(128) void k2_meta(
    const float* __restrict__ We1, const float* __restrict__ be1,
    const float* __restrict__ Wd1, const float* __restrict__ bd1,
    float* __restrict__ out)
{
    __shared__ float sWe[NC * 50];   // [c*50 + j]  (natural: We1 is [c][j])
    __shared__ float sWd[NC * 50];   // [c*50 + j]  (transposed: Wd1 is [j][c])
    __shared__ float sbe[50];
    __shared__ float sbd[NC];

    const int tid = threadIdx.x;
    for (int i = tid; i < NC * 50; i += 128) sWe[i] = We1[i];
    for (int i = tid; i < NC * 50; i += 128) {
        int c = i / 50, j = i % 50;
        sWd[i] = Wd1[j * NC + c];
    }
    if (tid < 50) sbe[tid] = be1[tid];
    if (tid < NC) sbd[tid] = bd1[tid];
    __syncthreads();

    const int r = blockIdx.x * 128 + tid;

    // hm packed: hm2[j2] holds (hm[2*j2], hm[2*j2+1])
    unsigned long long hm2[25];
    #pragma unroll
    for (int j = 0; j < 25; j++) hm2[j] = pk2(sbe[2 * j], sbe[2 * j + 1]);

    #pragma unroll 4
    for (int c = 0; c < NC; c++) {
        float e = g_errT[(size_t)c * BATCH + r];
        unsigned long long e2 = pk2(e, e);
        const unsigned long long* w = (const unsigned long long*)(sWe + c * 50);
        #pragma unroll
        for (int j = 0; j < 25; j++) hm2[j] = ffma2(e2, w[j], hm2[j]);
    }
    #pragma unroll
    for (int j = 0; j < 25; j++) {
        float lo, hi;
        upk2(lo, hi, hm2[j]);
        hm2[j] = pk2(fmaxf(lo, 0.f), fmaxf(hi, 0.f));
    }

    float acc = 0.f;
    #pragma unroll 2
    for (int c = 0; c < NC; c++) {
        const unsigned long long* w = (const unsigned long long*)(sWd + c * 50);
        unsigned long long rec2 = pk2(0.f, 0.f);
        #pragma unroll
        for (int j = 0; j < 25; j++) rec2 = ffma2(hm2[j], w[j], rec2);
        float lo, hi;
        upk2(lo, hi, rec2);
        float rec = lo + hi + sbd[c];
        float e = g_errT[(size_t)c * BATCH + r];
        float d = e - rec;
        acc = fmaf(d, d, acc);
    }

    float f = sqrtf(acc * 0.01f);
    out[r] = 1.f / (1.f + __expf(-f));
}

extern "C" void kernel_launch(void* const* d_in, const int* in_sizes, int n_in,
                              void* d_out, int out_size)
{
    const float* x        = (const float*)d_in[0];
    const int*   feat_idx = (const int*)  d_in[1];
    const float* W_enc    = (const float*)d_in[2];
    const float* b_enc    = (const float*)d_in[3];
    const float* W_dec    = (const float*)d_in[4];
    const float* b_dec    = (const float*)d_in[5];
    const float* We1      = (const float*)d_in[6];
    const float* be1      = (const float*)d_in[7];
    const float* Wd1      = (const float*)d_in[8];
    const float* bd1      = (const float*)d_in[9];
    float* out = (float*)d_out;

    const int smem1 = (RT * XP + 5000 + 500 + 5000 + 1000 + 1000) * 4; // 114064 B
    cudaFuncSetAttribute(k1_cluster, cudaFuncAttributeMaxDynamicSharedMemorySize, smem1);

    k1_cluster<<<K1_BLOCKS, K1_THREADS, smem1>>>(x, feat_idx, W_enc, b_enc, W_dec, b_dec);
    k2_meta<<<BATCH / 128, 128>>>(We1, be1, Wd1, bd1, out);
}

// round 4
// speedup vs baseline: 1.6327x; 1.1670x over previous
#include <cuda_runtime.h>
#include <math.h>

#define BATCH 65536
#define NC 100
#define RT 8            // rows per tile (per buffer) in k1
#define XP 1004         // padded x pitch in shared (multiple of 4 for cp.async16 alignment)
#define K1_THREADS 224
#define K1_BLOCKS 296   // 2 CTAs/SM * 148 SMs, persistent
#define N_TILES (BATCH / RT)   // 8192

// scratch: err transposed [cluster][row] so k2 reads coalesced
__device__ float g_errT[(size_t)NC * BATCH];

// ---------------- helpers ----------------
__device__ __forceinline__ unsigned long long pk2(float lo, float hi) {
    unsigned long long r;
    asm("mov.b64 %0, {%1, %2};" : "=l"(r) : "f"(lo), "f"(hi));
    return r;
}
__device__ __forceinline__ void upk2(float& lo, float& hi, unsigned long long v) {
    asm("mov.b64 {%0, %1}, %2;" : "=f"(lo), "=f"(hi) : "l"(v));
}
__device__ __forceinline__ unsigned long long ffma2(unsigned long long a,
                                                    unsigned long long b,
                                                    unsigned long long c) {
    unsigned long long d;
    asm("fma.rn.f32x2 %0, %1, %2, %3;" : "=l"(d) : "l"(a), "l"(b), "l"(c));
    return d;
}
__device__ __forceinline__ void cp_async16(float* smem_dst, const float4* gmem_src) {
    unsigned long long gp = (unsigned long long)gmem_src;
    unsigned sp;
    asm("{ .reg .u64 t; cvta.to.shared.u64 t, %1; cvt.u32.u64 %0, t; }"
        : "=r"(sp) : "l"(smem_dst));
    asm volatile("cp.async.cg.shared.global [%0], [%1], 16;" :: "r"(sp), "l"(gp));
}
__device__ __forceinline__ void cp_commit() {
    asm volatile("cp.async.commit_group;" ::: "memory");
}
__device__ __forceinline__ void cp_wait1() {
    asm volatile("cp.async.wait_group 1;" ::: "memory");
}

// ---------------------------------------------------------------------------
// Kernel 1: per-cluster autoencoders -> errT[c][row]. Persistent blocks.
// Double-buffered x staging via cp.async: stage tile t+1 while computing t.
// 200 compute tasks/tile: task=tid, c=tid>>1, q=tid&1 (rows q*4..q*4+3).
// Weight LDS conflict-free: 16 distinct c per warp, stride 50 -> 2*(9c mod 16).
// ---------------------------------------------------------------------------
__global__ __launch_bounds__(K1_THREADS, 2) void k1_cluster(
    const float* __restrict__ x, const int* __restrict__ feat_idx,
    const float* __restrict__ W_enc, const float* __restrict__ b_enc,
    const float* __restrict__ W_dec, const float* __restrict__ b_dec)
{
    extern __shared__ float smem[];
    float* sx  = smem;                  // 2 * RT * XP = 16064 floats
    float* sWe = sx + 2 * RT * XP;      // 5000: [c][m][j]
    float* sbe = sWe + 5000;            // 500:  [c][j]
    float* sWd = sbe + 500;             // 5000: [c][j][m]
    float* sbd = sWd + 5000;            // 1000: [c][m]
    int*   sfid = (int*)(sbd + 1000);   // 1000: [c][m]

    const int tid = threadIdx.x;

    // prologue: async-stage first tile into buffer 0 (overlaps weight staging)
    {
        const int t0 = blockIdx.x;
        const float4* xsrc = (const float4*)(x + (size_t)t0 * RT * 1000);
        for (int i = tid; i < RT * 250; i += K1_THREADS) {
            int r = i / 250, c4 = i % 250;
            cp_async16(sx + r * XP + c4 * 4, xsrc + r * 250 + c4);
        }
        cp_commit();
    }

    // one-time weight staging: straight copies
    for (int i = tid; i < 5000; i += K1_THREADS) sWe[i] = W_enc[i];
    for (int i = tid; i < 500;  i += K1_THREADS) sbe[i] = b_enc[i];
    for (int i = tid; i < 5000; i += K1_THREADS) sWd[i] = W_dec[i];
    for (int i = tid; i < 1000; i += K1_THREADS) sbd[i] = b_dec[i];
    for (int i = tid; i < 1000; i += K1_THREADS) sfid[i] = feat_idx[i];

    const int c_task = tid >> 1;
    const int q_task = tid & 1;

    int buf = 0;
    for (int t = blockIdx.x; t < N_TILES; t += K1_BLOCKS) {
        // stage NEXT tile into the other buffer
        const int tn = t + K1_BLOCKS;
        if (tn < N_TILES) {
            const float4* xsrc = (const float4*)(x + (size_t)tn * RT * 1000);
            float* dst = sx + (buf ^ 1) * RT * XP;
            for (int i = tid; i < RT * 250; i += K1_THREADS) {
                int r = i / 250, c4 = i % 250;
                cp_async16(dst + r * XP + c4 * 4, xsrc + r * 250 + c4);
            }
        }
        cp_commit();
        cp_wait1();          // tile t's data has landed
        __syncthreads();

        if (tid < 2 * NC) {
            const int c = c_task;
            const float* xq = sx + buf * RT * XP + q_task * 4 * XP;

            int fid[10];
            #pragma unroll
            for (int m = 0; m < 10; m++) fid[m] = sfid[c * 10 + m];

            float xg[4][10];
            #pragma unroll
            for (int m = 0; m < 10; m++)
                #pragma unroll
                for (int r = 0; r < 4; r++)
                    xg[r][m] = xq[r * XP + fid[m]];

            float h[4][5];
            #pragma unroll
            for (int j = 0; j < 5; j++) {
                float b = sbe[c * 5 + j];
                #pragma unroll
                for (int r = 0; r < 4; r++) h[r][j] = b;
            }
            #pragma unroll
            for (int m = 0; m < 10; m++)
                #pragma unroll
                for (int j = 0; j < 5; j++) {
                    float w = sWe[c * 50 + m * 5 + j];
                    #pragma unroll
                    for (int r = 0; r < 4; r++) h[r][j] = fmaf(xg[r][m], w, h[r][j]);
                }
            #pragma unroll
            for (int j = 0; j < 5; j++)
                #pragma unroll
                for (int r = 0; r < 4; r++) h[r][j] = fmaxf(h[r][j], 0.f);

            float acc[4] = {0.f, 0.f, 0.f, 0.f};
            #pragma unroll
            for (int m = 0; m < 10; m++) {
                float b = sbd[c * 10 + m];
                float rec[4];
                #pragma unroll
                for (int r = 0; r < 4; r++) rec[r] = b;
                #pragma unroll
                for (int j = 0; j < 5; j++) {
                    float w = sWd[c * 50 + j * 10 + m];
                    #pragma unroll
                    for (int r = 0; r < 4; r++) rec[r] = fmaf(h[r][j], w, rec[r]);
                }
                #pragma unroll
                for (int r = 0; r < 4; r++) {
                    float d = xg[r][m] - rec[r];
                    acc[r] = fmaf(d, d, acc[r]);
                }
            }
            float4 o;
            o.x = sqrtf(acc[0] * 0.1f);
            o.y = sqrtf(acc[1] * 0.1f);
            o.z = sqrtf(acc[2] * 0.1f);
            o.w = sqrtf(acc[3] * 0.1f);
            *(float4*)&g_errT[(size_t)c * BATCH + t * RT + q_task * 4] = o;
        }
        __syncthreads();     // all readers of buf done before it is re-staged
        buf ^= 1;
    }
}

// ---------------------------------------------------------------------------
// Kernel 2: meta autoencoder. 2 rows/thread (r, r+32768), fma.rn.f32x2.
// Halves weight-LDS per row (k2 is LDS-throughput bound).
// ---------------------------------------------------------------------------
__global__ __launch_bounds__(128) void k2_meta(
    const float* __restrict__ We1, const float* __restrict__ be1,
    const float* __restrict__ Wd1, const float* __restrict__ bd1,
    float* __restrict__ out)
{
    __shared__ float sWe[NC * 50];   // [c*50 + j]  (natural: We1 is [c][j])
    __shared__ float sWd[NC * 50];   // [c*50 + j]  (transposed: Wd1 is [j][c])
    __shared__ float sbe[50];
    __shared__ float sbd[NC];

    const int tid = threadIdx.x;
    for (int i = tid; i < NC * 50; i += 128) sWe[i] = We1[i];
    for (int i = tid; i < NC * 50; i += 128) {
        int c = i / 50, j = i % 50;
        sWd[i] = Wd1[j * NC + c];
    }
    if (tid < 50) sbe[tid] = be1[tid];
    if (tid < NC) sbd[tid] = bd1[tid];
    __syncthreads();

    const int r0 = blockIdx.x * 128 + tid;
    const int r1 = r0 + BATCH / 2;

    unsigned long long hma[25], hmb[25];
    #pragma unroll
    for (int j = 0; j < 25; j++) {
        unsigned long long b = pk2(sbe[2 * j], sbe[2 * j + 1]);
        hma[j] = b; hmb[j] = b;
    }

    #pragma unroll 2
    for (int c = 0; c < NC; c++) {
        float e0 = g_errT[(size_t)c * BATCH + r0];
        float e1 = g_errT[(size_t)c * BATCH + r1];
        unsigned long long e02 = pk2(e0, e0);
        unsigned long long e12 = pk2(e1, e1);
        const unsigned long long* w = (const unsigned long long*)(sWe + c * 50);
        #pragma unroll
        for (int j = 0; j < 25; j++) {
            unsigned long long wv = w[j];
            hma[j] = ffma2(e02, wv, hma[j]);
            hmb[j] = ffma2(e12, wv, hmb[j]);
        }
    }
    #pragma unroll
    for (int j = 0; j < 25; j++) {
        float lo, hi;
        upk2(lo, hi, hma[j]);
        hma[j] = pk2(fmaxf(lo, 0.f), fmaxf(hi, 0.f));
        upk2(lo, hi, hmb[j]);
        hmb[j] = pk2(fmaxf(lo, 0.f), fmaxf(hi, 0.f));
    }

    float acc0 = 0.f, acc1 = 0.f;
    #pragma unroll 2
    for (int c = 0; c < NC; c++) {
        const unsigned long long* w = (const unsigned long long*)(sWd + c * 50);
        unsigned long long ra = pk2(0.f, 0.f);
        unsigned long long rb = pk2(0.f, 0.f);
        #pragma unroll
        for (int j = 0; j < 25; j++) {
            unsigned long long wv = w[j];
            ra = ffma2(hma[j], wv, ra);
            rb = ffma2(hmb[j], wv, rb);
        }
        float lo, hi;
        upk2(lo, hi, ra);
        float rec0 = lo + hi + sbd[c];
        upk2(lo, hi, rb);
        float rec1 = lo + hi + sbd[c];
        float e0 = g_errT[(size_t)c * BATCH + r0];
        float e1 = g_errT[(size_t)c * BATCH + r1];
        float d0 = e0 - rec0, d1 = e1 - rec1;
        acc0 = fmaf(d0, d0, acc0);
        acc1 = fmaf(d1, d1, acc1);
    }

    float f0 = sqrtf(acc0 * 0.01f);
    float f1 = sqrtf(acc1 * 0.01f);
    out[r0] = 1.f / (1.f + __expf(-f0));
    out[r1] = 1.f / (1.f + __expf(-f1));
}

extern "C" void kernel_launch(void* const* d_in, const int* in_sizes, int n_in,
                              void* d_out, int out_size)
{
    const float* x        = (const float*)d_in[0];
    const int*   feat_idx = (const int*)  d_in[1];
    const float* W_enc    = (const float*)d_in[2];
    const float* b_enc    = (const float*)d_in[3];
    const float* W_dec    = (const float*)d_in[4];
    const float* b_dec    = (const float*)d_in[5];
    const float* We1      = (const float*)d_in[6];
    const float* be1      = (const float*)d_in[7];
    const float* Wd1      = (const float*)d_in[8];
    const float* bd1      = (const float*)d_in[9];
    float* out = (float*)d_out;

    const int smem1 = (2 * RT * XP + 5000 + 500 + 5000 + 1000 + 1000) * 4; // 114256 B
    cudaFuncSetAttribute(k1_cluster, cudaFuncAttributeMaxDynamicSharedMemorySize, smem1);

    k1_cluster<<<K1_BLOCKS, K1_THREADS, smem1>>>(x, feat_idx, W_enc, b_enc, W_dec, b_dec);
    k2_meta<<<BATCH / 256, 128>>>(We1, be1, Wd1, bd1, out);
}